// round 6
// baseline (speedup 1.0000x reference)
#include <cuda_runtime.h>
#include <cstdint>

#define C64    64
#define HW     224
#define HP     226
#define NB     8
#define NPIX   (NB * HW * HW)
#define EPS_BN 1e-5f
#define LEAK   0.1f
#define CEILV  255.0f

#define NTILE  1792            /* 8 b * 224 rows; tile = full row, 224px x 64oc */
#define NCTA   148
#define NTHR   448             /* 14 warps: 7 m x 2 n */

// SMEM float-index layout
#define SM_BIAS 0              /* 64 floats */
#define SM_RED  64             /* 128 floats: sum[64], ssq[64] */
#define SM_B    192            /* 36*64*16 = 36864 floats */
#define SM_A    37056          /* 3 rows * 226 px * 16 ch = 10848 floats */
#define SM_FLTS (37056 + 10848)
#define SMEM_DYN (SM_FLTS * 4) /* 191616 B */

#define AROW    3616           /* 226 px * 16 floats */

// permutation within each 16-channel group: slot = (c&3)*4 + ((c>>2)&3)
#define PERM16(c) (((c) & ~15) | (((c) & 3) << 2) | (((c) >> 2) & 3))

// ---------------- device scratch ----------------
__device__ __align__(16) float  g_xpad[NB * HP * HP * C64];  // padded NHWC, permuted ch
__device__ __align__(16) float  g_wB[36 * 64 * 16];          // [q*9+tap][o][slot16] tf32
__device__ double g_sum[C64];
__device__ double g_ssq[C64];
__device__ float  g_scale[C64];
__device__ float  g_shift[C64];

static __device__ __forceinline__ uint32_t tf32_rna(float x) {
    uint32_t u;
    asm("cvt.rna.tf32.f32 %0, %1;" : "=r"(u) : "f"(x));
    return u;
}
static __device__ __forceinline__ uint32_t fu(float x) { return __float_as_uint(x); }

static __device__ __forceinline__ void mma8(float* d, const uint32_t* a,
                                            const uint32_t* b) {
    asm volatile(
        "mma.sync.aligned.m16n8k8.row.col.f32.tf32.tf32.f32 "
        "{%0,%1,%2,%3},{%4,%5,%6,%7},{%8,%9},{%0,%1,%2,%3};"
        : "+f"(d[0]), "+f"(d[1]), "+f"(d[2]), "+f"(d[3])
        : "r"(a[0]), "r"(a[1]), "r"(a[2]), "r"(a[3]), "r"(b[0]), "r"(b[1]));
}

// ---------------- kernel: fold 3x3-ternary + 1x1, emit permuted tf32 -----
__global__ void fold_k(const float* __restrict__ w1x1,
                       const float* __restrict__ w_bin) {
    int t = blockIdx.x * 256 + threadIdx.x;
    if (t < C64) { g_sum[t] = 0.0; g_ssq[t] = 0.0; }
    if (t >= 64 * 9 * 64) return;
    int o = t & 63;
    int k = (t >> 6) % 9;        // tap
    int i = t / 576;             // in channel
    float s = 0.f;
    #pragma unroll 8
    for (int m = 0; m < 64; ++m)
        s += w1x1[o * 64 + m] * w_bin[(m * 64 + i) * 9 + k];
    int q = i >> 4, c16 = i & 15;
    int slot = (c16 & 3) * 4 + (c16 >> 2);
    g_wB[((q * 9 + k) * 64 + o) * 16 + slot] = __uint_as_float(tf32_rna(s));
}

// ---------------- kernel: zero padded border ----------------
__global__ void pad_zero() {
    int p = blockIdx.x;      // 0..899
    int b = blockIdx.y;
    int hp, wp;
    if (p < 226)      { hp = 0;   wp = p; }
    else if (p < 452) { hp = 225; wp = p - 226; }
    else { int q = p - 452; hp = 1 + (q >> 1); wp = (q & 1) * 225; }
    g_xpad[(((size_t)b * HP + hp) * HP + wp) * 64 + threadIdx.x] = 0.f;
}

// ---------------- kernel: NCHW -> padded NHWC, tf32-rounded, permuted ----
__global__ void pad_tr(const float* __restrict__ x) {
    __shared__ float s[64][33];
    int lx = threadIdx.x, ly = threadIdx.y;   // 32, 8
    int w0 = blockIdx.x * 32, h = blockIdx.y, b = blockIdx.z;
    #pragma unroll
    for (int i = 0; i < 8; ++i) {
        int c = i * 8 + ly;
        s[c][lx] = x[(((size_t)b * 64 + c) * HW + h) * HW + w0 + lx];
    }
    __syncthreads();
    float* dst = g_xpad + (((size_t)b * HP + h + 1) * HP + w0 + 1) * 64;
    #pragma unroll
    for (int jj = 0; jj < 8; ++jj) {
        int f = jj * 256 + ly * 32 + lx;
        int ch = f & 63, px = f >> 6;
        dst[(size_t)px * 64 + PERM16(ch)] = __uint_as_float(tf32_rna(s[ch][px]));
    }
}

// ---------------- kernel: tf32 mma.sync implicit-GEMM conv + BN stats ----
// Persistent 148 CTAs x 448 thr (14 warps: 7m x 2n). Tile = full row:
// D[224px x 64oc], K = 4 quarters x 16ch x 9 taps. A staged per quarter.
__global__ __launch_bounds__(NTHR, 1)
void conv_mma(const float* __restrict__ bias, float* __restrict__ out) {
    extern __shared__ __align__(16) float sm[];
    float* Bs = sm + SM_B;
    float* As = sm + SM_A;
    const int tid = threadIdx.x;
    const int lane = tid & 31, wid = tid >> 5;
    const int wn = wid & 1, wm = wid >> 1;       // 7 m-warps x 2 n-warps
    const int gr = lane >> 2, gc = lane & 3;

    // weights + bias -> SMEM once; zero reduction slots
    for (int i = tid; i < 9216; i += NTHR)
        ((float4*)Bs)[i] = ((const float4*)g_wB)[i];
    if (tid < 64) sm[SM_BIAS + tid] = bias[tid];
    if (tid < 128) sm[SM_RED + tid] = 0.f;

    float ps[4][2], qs[4][2];   // per-thread BN partials (8 fixed o-slots)
    #pragma unroll
    for (int ns = 0; ns < 4; ++ns)
        ps[ns][0] = ps[ns][1] = qs[ns][0] = qs[ns][1] = 0.f;

    for (int j = 0; j < 13; ++j) {
        int t = j * NCTA + blockIdx.x;
        if (t >= NTILE) break;
        int b = t / 224, h = t % 224;
        const float* xrow = g_xpad + (((size_t)b * HP + h) * HP) * 64;

        float acc[2][4][4];
        #pragma unroll
        for (int ms = 0; ms < 2; ++ms)
            #pragma unroll
            for (int ns = 0; ns < 4; ++ns)
                #pragma unroll
                for (int q2 = 0; q2 < 4; ++q2) acc[ms][ns][q2] = 0.f;

        #pragma unroll
        for (int q = 0; q < 4; ++q) {
            __syncthreads();   // previous readers done
            // stage A: 3 rows x 226 px x 16 ch (quarter q), px stride 16
            for (int i = tid; i < 2712; i += NTHR) {
                int r = i / 904, rem = i % 904;
                int px = rem >> 2, c4 = rem & 3;
                float4 v = *(const float4*)(xrow + ((size_t)r * HP + px) * 64
                                            + q * 16 + c4 * 4);
                *(float4*)&As[r * AROW + px * 16 + c4 * 4] = v;
            }
            __syncthreads();

            #pragma unroll
            for (int kh = 0; kh < 3; ++kh) {
                #pragma unroll
                for (int kw = 0; kw < 3; ++kw) {
                    uint32_t Ae[2][4], Ao[2][4];
                    #pragma unroll
                    for (int ms = 0; ms < 2; ++ms) {
                        const float* ap = As + kh * AROW
                            + (wm * 32 + ms * 16 + gr + kw) * 16 + gc * 4;
                        float4 lo = *(const float4*)ap;
                        float4 hi = *(const float4*)(ap + 8 * 16);
                        Ae[ms][0] = fu(lo.x); Ae[ms][1] = fu(hi.x);
                        Ae[ms][2] = fu(lo.y); Ae[ms][3] = fu(hi.y);
                        Ao[ms][0] = fu(lo.z); Ao[ms][1] = fu(hi.z);
                        Ao[ms][2] = fu(lo.w); Ao[ms][3] = fu(hi.w);
                    }
                    const float* bp = Bs
                        + ((q * 9 + kh * 3 + kw) * 64 + wn * 32 + gr) * 16
                        + gc * 4;
                    #pragma unroll
                    for (int ns = 0; ns < 4; ++ns) {
                        float4 bv = *(const float4*)(bp + ns * 128);
                        uint32_t Be[2] = { fu(bv.x), fu(bv.y) };
                        uint32_t Bo[2] = { fu(bv.z), fu(bv.w) };
                        mma8(acc[0][ns], Ae[0], Be);
                        mma8(acc[1][ns], Ae[1], Be);
                        mma8(acc[0][ns], Ao[0], Bo);
                        mma8(acc[1][ns], Ao[1], Bo);
                    }
                }
            }
        }

        // epilogue: + bias, NCHW store, BN partials (no overlap now)
        const size_t chstr = (size_t)HW * HW;
        const int pxb = wm * 32 + gr;
        const int ob  = wn * 32 + gc * 2;
        float* obase = out + ((size_t)b * 64) * chstr + (size_t)h * HW;
        #pragma unroll
        for (int ms = 0; ms < 2; ++ms) {
            #pragma unroll
            for (int ns = 0; ns < 4; ++ns) {
                int o0 = ob + ns * 8;
                float b0 = sm[SM_BIAS + o0], b1 = sm[SM_BIAS + o0 + 1];
                float y0 = acc[ms][ns][0] + b0;
                float y1 = acc[ms][ns][1] + b1;
                float y2 = acc[ms][ns][2] + b0;
                float y3 = acc[ms][ns][3] + b1;
                float* p = obase + (size_t)o0 * chstr + pxb + ms * 16;
                p[0]         = y0;
                p[chstr]     = y1;
                p[8]         = y2;
                p[chstr + 8] = y3;
                ps[ns][0] += y0 + y2;  qs[ns][0] += y0 * y0 + y2 * y2;
                ps[ns][1] += y1 + y3;  qs[ns][1] += y1 * y1 + y3 * y3;
            }
        }
    }

    // BN partial reduction: regs -> shared -> global doubles
    #pragma unroll
    for (int ns = 0; ns < 4; ++ns) {
        int o0 = wn * 32 + ns * 8 + gc * 2;
        atomicAdd(&sm[SM_RED + o0],          ps[ns][0]);
        atomicAdd(&sm[SM_RED + o0 + 1],      ps[ns][1]);
        atomicAdd(&sm[SM_RED + 64 + o0],     qs[ns][0]);
        atomicAdd(&sm[SM_RED + 64 + o0 + 1], qs[ns][1]);
    }
    __syncthreads();
    if (tid < 64) {
        atomicAdd(&g_sum[tid], (double)sm[SM_RED + tid]);
        atomicAdd(&g_ssq[tid], (double)sm[SM_RED + 64 + tid]);
    }
}

// ---------------- kernel: finalize BN ----------------
__global__ void stats_k(const float* __restrict__ gamma,
                        const float* __restrict__ beta) {
    int c = threadIdx.x;
    if (c >= C64) return;
    double m = g_sum[c] / (double)NPIX;
    double v = g_ssq[c] / (double)NPIX - m * m;
    float a = gamma[c] * rsqrtf((float)v + EPS_BN);
    g_scale[c] = a;
    g_shift[c] = beta[c] - (float)m * a;
}

// ---------------- kernel: normalize + leaky relu + clamp ----------------
__global__ void act_k(float* __restrict__ out) {
    int idx = blockIdx.x * blockDim.x + threadIdx.x;
    const int total4 = NB * C64 * HW * HW / 4;
    if (idx >= total4) return;
    int plane = (idx * 4) / (HW * HW);
    int c = plane & 63;
    float a = g_scale[c], sh = g_shift[c];
    float4 v = ((float4*)out)[idx];
    float* vp = &v.x;
    #pragma unroll
    for (int p = 0; p < 4; ++p) {
        float y = a * vp[p] + sh;
        y = (y >= 0.f) ? y : LEAK * y;
        y = fminf(fmaxf(y, 0.f), CEILV);
        vp[p] = y;
    }
    ((float4*)out)[idx] = v;
}

// ---------------- launch ----------------
extern "C" void kernel_launch(void* const* d_in, const int* in_sizes, int n_in,
                              void* d_out, int out_size) {
    const float* x     = (const float*)d_in[0];
    const float* w_bin = (const float*)d_in[1];
    const float* w1x1  = (const float*)d_in[2];
    const float* b1x1  = (const float*)d_in[3];
    const float* gamma = (const float*)d_in[4];
    const float* beta  = (const float*)d_in[5];
    float* out = (float*)d_out;

    cudaFuncSetAttribute(conv_mma, cudaFuncAttributeMaxDynamicSharedMemorySize,
                         SMEM_DYN);

    fold_k<<<(64 * 9 * 64 + 255) / 256, 256>>>(w1x1, w_bin);
    pad_zero<<<dim3(900, NB), 64>>>();
    pad_tr<<<dim3(7, HW, NB), dim3(32, 8)>>>(x);
    conv_mma<<<NCTA, NTHR, SMEM_DYN>>>(b1x1, out);
    stats_k<<<1, 64>>>(gamma, beta);
    int total4 = NB * C64 * HW * HW / 4;
    act_k<<<(total4 + 255) / 256, 256>>>(out);
}

// round 7
// speedup vs baseline: 1.2790x; 1.2790x over previous
#include <cuda_runtime.h>
#include <cstdint>

#define C64    64
#define HW     224
#define HP     226
#define NB     8
#define NPIX   (NB * HW * HW)
#define EPS_BN 1e-5f
#define LEAK   0.1f
#define CEILV  255.0f

#define NTILE  1792            /* 8 b * 224 rows; tile = full row, 224px x 64oc */
#define NCTA   148
#define NTHR   448             /* 14 warps: 7 m x 2 n */

// SMEM float-index layout
#define SM_BIAS 0              /* 64 floats */
#define SM_RED  64             /* 128 floats: sum[64], ssq[64] */
#define SM_B    192            /* 72*64*8 = 36864 floats */
#define SM_A    37056          /* 3 bufs x (3 rows * 226 px * 8 ch) */
#define ABUF    5424           /* floats per A buffer */
#define SM_FLTS (37056 + 3 * ABUF)
#define SMEM_DYN (SM_FLTS * 4) /* 213312 B */

#define AROW    1808           /* 226 px * 8 floats */

// permutation within each 8-channel group: slot = (c&3)*2 + (c>>2)
#define PERM64(c) (((c) & ~7) | (((c) & 3) << 1) | (((c) >> 2) & 1))

// ---------------- device scratch ----------------
__device__ __align__(16) float  g_xpad[NB * HP * HP * C64];  // padded NHWC, permuted ch
__device__ __align__(16) float  g_wB[72 * 64 * 8];           // [q8*9+tap][o][slot8]
__device__ double g_sum[C64];
__device__ double g_ssq[C64];
__device__ float  g_scale[C64];
__device__ float  g_shift[C64];

static __device__ __forceinline__ uint32_t tf32_rna(float x) {
    uint32_t u;
    asm("cvt.rna.tf32.f32 %0, %1;" : "=r"(u) : "f"(x));
    return u;
}
static __device__ __forceinline__ uint32_t fu(float x) { return __float_as_uint(x); }

static __device__ __forceinline__ void mma8(float* d, const uint32_t* a,
                                            const uint32_t* b) {
    asm volatile(
        "mma.sync.aligned.m16n8k8.row.col.f32.tf32.tf32.f32 "
        "{%0,%1,%2,%3},{%4,%5,%6,%7},{%8,%9},{%0,%1,%2,%3};"
        : "+f"(d[0]), "+f"(d[1]), "+f"(d[2]), "+f"(d[3])
        : "r"(a[0]), "r"(a[1]), "r"(a[2]), "r"(a[3]), "r"(b[0]), "r"(b[1]));
}
static __device__ __forceinline__ void cp16(uint32_t dst, const void* src) {
    asm volatile("cp.async.cg.shared.global [%0], [%1], 16;"
                 :: "r"(dst), "l"(src));
}

// ---------------- kernel: fold 3x3-ternary + 1x1, emit permuted tf32 -----
__global__ void fold_k(const float* __restrict__ w1x1,
                       const float* __restrict__ w_bin) {
    int t = blockIdx.x * 256 + threadIdx.x;
    if (t < C64) { g_sum[t] = 0.0; g_ssq[t] = 0.0; }
    if (t >= 64 * 9 * 64) return;
    int o = t & 63;
    int k = (t >> 6) % 9;        // tap
    int i = t / 576;             // in channel
    float s = 0.f;
    #pragma unroll 8
    for (int m = 0; m < 64; ++m)
        s += w1x1[o * 64 + m] * w_bin[(m * 64 + i) * 9 + k];
    int q8 = i >> 3, c8 = i & 7;
    int slot = (c8 & 3) * 2 + (c8 >> 2);
    g_wB[((q8 * 9 + k) * 64 + o) * 8 + slot] = __uint_as_float(tf32_rna(s));
}

// ---------------- kernel: zero padded border ----------------
__global__ void pad_zero() {
    int p = blockIdx.x;      // 0..899
    int b = blockIdx.y;
    int hp, wp;
    if (p < 226)      { hp = 0;   wp = p; }
    else if (p < 452) { hp = 225; wp = p - 226; }
    else { int q = p - 452; hp = 1 + (q >> 1); wp = (q & 1) * 225; }
    g_xpad[(((size_t)b * HP + hp) * HP + wp) * 64 + threadIdx.x] = 0.f;
}

// ---------------- kernel: NCHW -> padded NHWC, tf32-rounded, permuted ----
__global__ void pad_tr(const float* __restrict__ x) {
    __shared__ float s[64][33];
    int lx = threadIdx.x, ly = threadIdx.y;   // 32, 8
    int w0 = blockIdx.x * 32, h = blockIdx.y, b = blockIdx.z;
    #pragma unroll
    for (int i = 0; i < 8; ++i) {
        int c = i * 8 + ly;
        s[c][lx] = x[(((size_t)b * 64 + c) * HW + h) * HW + w0 + lx];
    }
    __syncthreads();
    float* dst = g_xpad + (((size_t)b * HP + h + 1) * HP + w0 + 1) * 64;
    #pragma unroll
    for (int jj = 0; jj < 8; ++jj) {
        int f = jj * 256 + ly * 32 + lx;
        int ch = f & 63, px = f >> 6;
        dst[(size_t)px * 64 + PERM64(ch)] = __uint_as_float(tf32_rna(s[ch][px]));
    }
}

// ---------------- kernel: cp.async-pipelined tf32 mma conv + BN stats ----
// Persistent 148 CTAs x 448 thr (7m x 2n warps). Tile = full row 224px x 64oc.
// K split into 8 stages of 8 ch; A triple-buffered, distance-1 prefetch.
__global__ __launch_bounds__(NTHR, 1)
void conv_mma(const float* __restrict__ bias, float* __restrict__ out) {
    extern __shared__ __align__(16) float sm[];
    float* Bs = sm + SM_B;
    float* As = sm + SM_A;
    const int tid = threadIdx.x;
    const int lane = tid & 31, wid = tid >> 5;
    const int wn = wid & 1, wm = wid >> 1;       // 7 m-warps x 2 n-warps
    const int gr = lane >> 2, gc = lane & 3;
    const uint32_t a_smem = (uint32_t)__cvta_generic_to_shared(As);

    // weights + bias -> SMEM once; zero reduction slots
    for (int i = tid; i < 9216; i += NTHR)
        ((float4*)Bs)[i] = ((const float4*)g_wB)[i];
    if (tid < 64) sm[SM_BIAS + tid] = bias[tid];
    if (tid < 128) sm[SM_RED + tid] = 0.f;

    const int ntiles = (NTILE - blockIdx.x + NCTA - 1) / NCTA;
    const int nstage = ntiles * 8;

    // stage issuer: tile g>>3, channel group g&7, buffer g%3
    auto issue = [&](int g) {
        int t = (g >> 3) * NCTA + blockIdx.x;
        int q8 = g & 7;
        const float* xrow = g_xpad
            + (((size_t)(t / 224) * HP + (t % 224)) * HP) * 64 + q8 * 8;
        uint32_t dst = a_smem + (uint32_t)(g % 3) * (ABUF * 4);
        #pragma unroll
        for (int i = tid; i < 1356; i += NTHR) {
            int r = i / 452, rem = i % 452;
            int px = rem >> 1, c4 = rem & 1;
            cp16(dst + (uint32_t)(r * AROW + px * 8 + c4 * 4) * 4,
                 xrow + ((size_t)r * HP + px) * 64 + c4 * 4);
        }
        asm volatile("cp.async.commit_group;");
    };

    float ps[4][2], qs[4][2];   // per-thread BN partials
    #pragma unroll
    for (int ns = 0; ns < 4; ++ns)
        ps[ns][0] = ps[ns][1] = qs[ns][0] = qs[ns][1] = 0.f;

    float acc[2][4][4];

    issue(0);

    for (int g = 0; g < nstage; ++g) {
        if (g + 1 < nstage) {
            issue(g + 1);
            asm volatile("cp.async.wait_group 1;");
        } else {
            asm volatile("cp.async.wait_group 0;");
        }
        __syncthreads();

        const int q8 = g & 7;
        if (q8 == 0) {
            #pragma unroll
            for (int ms = 0; ms < 2; ++ms)
                #pragma unroll
                for (int ns = 0; ns < 4; ++ns)
                    #pragma unroll
                    for (int q2 = 0; q2 < 4; ++q2) acc[ms][ns][q2] = 0.f;
        }

        const float* Ab = As + (g % 3) * ABUF;
        const float* Bq = Bs + q8 * 4608;   // 9 taps * 512
        #pragma unroll
        for (int kh = 0; kh < 3; ++kh) {
            #pragma unroll
            for (int kw = 0; kw < 3; ++kw) {
                const float* ap = Ab + kh * AROW
                    + (wm * 32 + gr + kw) * 8 + gc * 2;
                float2 a00 = *(const float2*)ap;
                float2 a01 = *(const float2*)(ap + 64);
                float2 a10 = *(const float2*)(ap + 128);
                float2 a11 = *(const float2*)(ap + 192);
                uint32_t A0[4] = { fu(a00.x), fu(a01.x), fu(a00.y), fu(a01.y) };
                uint32_t A1[4] = { fu(a10.x), fu(a11.x), fu(a10.y), fu(a11.y) };
                const float* bp = Bq
                    + ((kh * 3 + kw) * 64 + wn * 32 + gr) * 8 + gc * 2;
                #pragma unroll
                for (int ns = 0; ns < 4; ++ns) {
                    float2 bv = *(const float2*)(bp + ns * 64);
                    uint32_t Bf[2] = { fu(bv.x), fu(bv.y) };
                    mma8(acc[0][ns], A0, Bf);
                    mma8(acc[1][ns], A1, Bf);
                }
            }
        }

        if (q8 == 7) {
            // epilogue: + bias, NCHW store, BN partials
            int t = (g >> 3) * NCTA + blockIdx.x;
            int b = t / 224, h = t % 224;
            const size_t chstr = (size_t)HW * HW;
            const int pxb = wm * 32 + gr;
            const int ob  = wn * 32 + gc * 2;
            float* obase = out + ((size_t)b * 64) * chstr + (size_t)h * HW;
            #pragma unroll
            for (int ms = 0; ms < 2; ++ms) {
                #pragma unroll
                for (int ns = 0; ns < 4; ++ns) {
                    int o0 = ob + ns * 8;
                    float b0 = sm[SM_BIAS + o0], b1 = sm[SM_BIAS + o0 + 1];
                    float y0 = acc[ms][ns][0] + b0;
                    float y1 = acc[ms][ns][1] + b1;
                    float y2 = acc[ms][ns][2] + b0;
                    float y3 = acc[ms][ns][3] + b1;
                    float* p = obase + (size_t)o0 * chstr + pxb + ms * 16;
                    p[0]         = y0;
                    p[chstr]     = y1;
                    p[8]         = y2;
                    p[chstr + 8] = y3;
                    ps[ns][0] += y0 + y2;  qs[ns][0] += y0 * y0 + y2 * y2;
                    ps[ns][1] += y1 + y3;  qs[ns][1] += y1 * y1 + y3 * y3;
                }
            }
        }
    }

    // BN partial reduction: regs -> shared -> global doubles
    #pragma unroll
    for (int ns = 0; ns < 4; ++ns) {
        int o0 = wn * 32 + ns * 8 + gc * 2;
        atomicAdd(&sm[SM_RED + o0],          ps[ns][0]);
        atomicAdd(&sm[SM_RED + o0 + 1],      ps[ns][1]);
        atomicAdd(&sm[SM_RED + 64 + o0],     qs[ns][0]);
        atomicAdd(&sm[SM_RED + 64 + o0 + 1], qs[ns][1]);
    }
    __syncthreads();
    if (tid < 64) {
        atomicAdd(&g_sum[tid], (double)sm[SM_RED + tid]);
        atomicAdd(&g_ssq[tid], (double)sm[SM_RED + 64 + tid]);
    }
}

// ---------------- kernel: finalize BN ----------------
__global__ void stats_k(const float* __restrict__ gamma,
                        const float* __restrict__ beta) {
    int c = threadIdx.x;
    if (c >= C64) return;
    double m = g_sum[c] / (double)NPIX;
    double v = g_ssq[c] / (double)NPIX - m * m;
    float a = gamma[c] * rsqrtf((float)v + EPS_BN);
    g_scale[c] = a;
    g_shift[c] = beta[c] - (float)m * a;
}

// ---------------- kernel: normalize + leaky relu + clamp ----------------
__global__ void act_k(float* __restrict__ out) {
    int idx = blockIdx.x * blockDim.x + threadIdx.x;
    const int total4 = NB * C64 * HW * HW / 4;
    if (idx >= total4) return;
    int plane = (idx * 4) / (HW * HW);
    int c = plane & 63;
    float a = g_scale[c], sh = g_shift[c];
    float4 v = ((float4*)out)[idx];
    float* vp = &v.x;
    #pragma unroll
    for (int p = 0; p < 4; ++p) {
        float y = a * vp[p] + sh;
        y = (y >= 0.f) ? y : LEAK * y;
        y = fminf(fmaxf(y, 0.f), CEILV);
        vp[p] = y;
    }
    ((float4*)out)[idx] = v;
}

// ---------------- launch ----------------
extern "C" void kernel_launch(void* const* d_in, const int* in_sizes, int n_in,
                              void* d_out, int out_size) {
    const float* x     = (const float*)d_in[0];
    const float* w_bin = (const float*)d_in[1];
    const float* w1x1  = (const float*)d_in[2];
    const float* b1x1  = (const float*)d_in[3];
    const float* gamma = (const float*)d_in[4];
    const float* beta  = (const float*)d_in[5];
    float* out = (float*)d_out;

    cudaFuncSetAttribute(conv_mma, cudaFuncAttributeMaxDynamicSharedMemorySize,
                         SMEM_DYN);

    fold_k<<<(64 * 9 * 64 + 255) / 256, 256>>>(w1x1, w_bin);
    pad_zero<<<dim3(900, NB), 64>>>();
    pad_tr<<<dim3(7, HW, NB), dim3(32, 8)>>>(x);
    conv_mma<<<NCTA, NTHR, SMEM_DYN>>>(b1x1, out);
    stats_k<<<1, 64>>>(gamma, beta);
    int total4 = NB * C64 * HW * HW / 4;
    act_k<<<(total4 + 255) / 256, 256>>>(out);
}